// round 7
// baseline (speedup 1.0000x reference)
#include <cuda_runtime.h>
#include <math.h>

#define MM 4096
#define DD 2048
#define INV_SQRT_M 0.015625f   // 1/sqrt(4096) exact

#define GRID_MV 512            // 8 row-triples per block
#define GRID_CP 1024           // 4 rows per block

// ---------------- device scratch ----------------
__device__ float g_qt[MM];
__device__ float g_k[MM];
__device__ float g_v[MM];
__device__ float g_it, g_ft, g_ot;
__device__ float g_kqt, g_denom;

__device__ __forceinline__ float dot4(float4 a, float4 b) {
    return a.x * b.x + a.y * b.y + a.z * b.z + a.w * b.w;
}

// ---------------- kernel 1: persistent pipelined q/k/v matvecs ----------------
// 512 blocks x 256 threads. Block b handles rows b + p*512, p = 0..7.
// Register double-buffer: while row p is reduced/written, row p+1's 6
// streaming loads are already in flight. Ping-pong smem, one sync per row.
__global__ __launch_bounds__(256) void mv_kernel(
    const float* __restrict__ x,
    const float* __restrict__ Wq, const float* __restrict__ bq,
    const float* __restrict__ Wk, const float* __restrict__ bk,
    const float* __restrict__ Wv, const float* __restrict__ bV)
{
    const int b = blockIdx.x;
    const int t = threadIdx.x;

    const float4* x4 = reinterpret_cast<const float4*>(x);
    const float4 x0 = x4[t];
    const float4 x1 = x4[t + 256];

    __shared__ float ws[2][3][8];

    float4 A[6], B[6];

    // preload row p=0
    {
        const size_t r = (size_t)b;
        const float4* Aq = reinterpret_cast<const float4*>(Wq + r * DD);
        const float4* Ak = reinterpret_cast<const float4*>(Wk + r * DD);
        const float4* Av = reinterpret_cast<const float4*>(Wv + r * DD);
        A[0] = __ldcs(&Aq[t]); A[1] = __ldcs(&Aq[t + 256]);
        A[2] = __ldcs(&Ak[t]); A[3] = __ldcs(&Ak[t + 256]);
        A[4] = __ldcs(&Av[t]); A[5] = __ldcs(&Av[t + 256]);
    }

    #pragma unroll
    for (int p = 0; p < 8; p++) {
        const int r = b + p * GRID_MV;
        // prefetch next row while current is processed
        if (p < 7) {
            const size_t rn = (size_t)(r + GRID_MV);
            const float4* Bq = reinterpret_cast<const float4*>(Wq + rn * DD);
            const float4* Bk = reinterpret_cast<const float4*>(Wk + rn * DD);
            const float4* Bv = reinterpret_cast<const float4*>(Wv + rn * DD);
            B[0] = __ldcs(&Bq[t]); B[1] = __ldcs(&Bq[t + 256]);
            B[2] = __ldcs(&Bk[t]); B[3] = __ldcs(&Bk[t + 256]);
            B[4] = __ldcs(&Bv[t]); B[5] = __ldcs(&Bv[t + 256]);
        }

        float sa = dot4(A[0], x0) + dot4(A[1], x1);
        float sk = dot4(A[2], x0) + dot4(A[3], x1);
        float sv = dot4(A[4], x0) + dot4(A[5], x1);

        #pragma unroll
        for (int o = 16; o > 0; o >>= 1) {
            sa += __shfl_down_sync(0xFFFFFFFFu, sa, o);
            sk += __shfl_down_sync(0xFFFFFFFFu, sk, o);
            sv += __shfl_down_sync(0xFFFFFFFFu, sv, o);
        }
        const int ph = p & 1;
        if ((t & 31) == 0) {
            const int w = t >> 5;
            ws[ph][0][w] = sa; ws[ph][1][w] = sk; ws[ph][2][w] = sv;
        }
        __syncthreads();
        if (t < 8) {
            float ra = ws[ph][0][t], rk = ws[ph][1][t], rv = ws[ph][2][t];
            #pragma unroll
            for (int o = 4; o > 0; o >>= 1) {
                ra += __shfl_down_sync(0xFFu, ra, o, 8);
                rk += __shfl_down_sync(0xFFu, rk, o, 8);
                rv += __shfl_down_sync(0xFFu, rv, o, 8);
            }
            if (t == 0) {
                g_qt[r] = ra + bq[r];
                g_k[r]  = INV_SQRT_M * (rk + bk[r]);
                g_v[r]  = rv + bV[r];
            }
        }
        // rotate buffers (register-renamed under full unroll)
        #pragma unroll
        for (int i = 0; i < 6; i++) A[i] = B[i];
    }
}

// ---------------- kernel 2: gates + n-update + tiny reductions ----------------
// Computes it/ft/ot from Wi/Wf/Wo, then
// n_i = ft*n_prev_i + it*k_i ; kqt = k·qt ; denom = max(|n·qt|, 1)
__global__ __launch_bounds__(1024) void nred_kernel(
    const float* __restrict__ x,
    const float* __restrict__ Wi, const float* __restrict__ bi,
    const float* __restrict__ Wf, const float* __restrict__ bf,
    const float* __restrict__ Wo, const float* __restrict__ bo,
    const float* __restrict__ n_prev, float* __restrict__ out_n)
{
    const int t = threadIdx.x;
    __shared__ float red[3][32];
    __shared__ float gates[2];

    // ---- gate dot products (2048 elems, 1024 threads -> 2 each) ----
    float si = 0.f, sf = 0.f, so = 0.f;
    #pragma unroll
    for (int u = 0; u < 2; u++) {
        const int i = t + u * 1024;
        const float xv = x[i];
        si += Wi[i] * xv;
        sf += Wf[i] * xv;
        so += Wo[i] * xv;
    }
    #pragma unroll
    for (int o = 16; o > 0; o >>= 1) {
        si += __shfl_down_sync(0xFFFFFFFFu, si, o);
        sf += __shfl_down_sync(0xFFFFFFFFu, sf, o);
        so += __shfl_down_sync(0xFFFFFFFFu, so, o);
    }
    if ((t & 31) == 0) {
        const int w = t >> 5;
        red[0][w] = si; red[1][w] = sf; red[2][w] = so;
    }
    __syncthreads();
    if (t < 32) {
        float a = red[0][t], b = red[1][t], c = red[2][t];
        #pragma unroll
        for (int o = 16; o > 0; o >>= 1) {
            a += __shfl_down_sync(0xFFFFFFFFu, a, o);
            b += __shfl_down_sync(0xFFFFFFFFu, b, o);
            c += __shfl_down_sync(0xFFFFFFFFu, c, o);
        }
        if (t == 0) {
            const float itv = expf(a + bi[0]);
            const float ftv = expf(b + bf[0]);
            const float z   = c + bo[0];
            g_it = itv; g_ft = ftv;
            g_ot = 1.0f / (1.0f + expf(-z));
            gates[0] = itv; gates[1] = ftv;
        }
    }
    __syncthreads();
    const float it = gates[0];
    const float ft = gates[1];

    // ---- n update + kqt / nqt reductions ----
    float kqt = 0.f, nqt = 0.f;
    #pragma unroll
    for (int u = 0; u < MM / 1024; u++) {
        const int i = t + u * 1024;
        const float k = g_k[i];
        const float q = g_qt[i];
        kqt += k * q;
        const float n = ft * n_prev[i] + it * k;
        out_n[i] = n;
        nqt += n * q;
    }
    #pragma unroll
    for (int o = 16; o > 0; o >>= 1) {
        kqt += __shfl_down_sync(0xFFFFFFFFu, kqt, o);
        nqt += __shfl_down_sync(0xFFFFFFFFu, nqt, o);
    }
    if ((t & 31) == 0) { red[0][t >> 5] = kqt; red[1][t >> 5] = nqt; }
    __syncthreads();
    if (t < 32) {
        float a = red[0][t], b = red[1][t];
        #pragma unroll
        for (int o = 16; o > 0; o >>= 1) {
            a += __shfl_down_sync(0xFFFFFFFFu, a, o);
            b += __shfl_down_sync(0xFFFFFFFFu, b, o);
        }
        if (t == 0) {
            g_kqt = a;
            g_denom = fmaxf(fabsf(b), 1.0f);
        }
    }
}

// ---------------- kernel 3: persistent pipelined cp stream ----------------
// 1024 blocks x 512 threads. Block b handles rows b + p*1024, p = 0..3.
// k/q loaded once (row-invariant per thread). 1-ahead register prefetch of
// the next cp row hides the per-row block reduce + sync.
__global__ __launch_bounds__(512) void cp_kernel(
    const float* __restrict__ cp, float* __restrict__ outC,
    float* __restrict__ outH)
{
    const int b = blockIdx.x;
    const int t = threadIdx.x;

    const float ft  = g_ft;
    const float itg = g_it;
    const float inv = g_ot / g_denom;
    const float kqt = g_kqt;

    float itv[4];
    #pragma unroll
    for (int p = 0; p < 4; p++) itv[p] = itg * g_v[b + p * GRID_CP];

    const float4* k4 = reinterpret_cast<const float4*>(g_k);
    const float4* q4 = reinterpret_cast<const float4*>(g_qt);
    const int j0 = t;
    const int j1 = t + 512;
    const float4 ka = k4[j0], kb = k4[j1];
    const float4 qa = q4[j0], qb = q4[j1];

    __shared__ float ws[2][16];

    float4 A0, A1, B0, B1;
    {
        const float4* P = reinterpret_cast<const float4*>(cp + (size_t)b * MM);
        A0 = __ldcs(&P[j0]);
        A1 = __ldcs(&P[j1]);
    }

    #pragma unroll
    for (int p = 0; p < 4; p++) {
        const int r = b + p * GRID_CP;
        if (p < 3) {
            const float4* P = reinterpret_cast<const float4*>(cp + (size_t)(r + GRID_CP) * MM);
            B0 = __ldcs(&P[j0]);
            B1 = __ldcs(&P[j1]);
        }

        float4* O = reinterpret_cast<float4*>(outC + (size_t)r * MM);
        const float iv = itv[p];
        float4 o;
        o.x = ft * A0.x + iv * ka.x; o.y = ft * A0.y + iv * ka.y;
        o.z = ft * A0.z + iv * ka.z; o.w = ft * A0.w + iv * ka.w;
        __stcs(&O[j0], o);
        o.x = ft * A1.x + iv * kb.x; o.y = ft * A1.y + iv * kb.y;
        o.z = ft * A1.z + iv * kb.z; o.w = ft * A1.w + iv * kb.w;
        __stcs(&O[j1], o);

        float s = dot4(A0, qa) + dot4(A1, qb);
        #pragma unroll
        for (int o2 = 16; o2 > 0; o2 >>= 1)
            s += __shfl_down_sync(0xFFFFFFFFu, s, o2);
        const int ph = p & 1;
        if ((t & 31) == 0) ws[ph][t >> 5] = s;
        __syncthreads();
        if (t < 16) {
            float a = ws[ph][t];
            #pragma unroll
            for (int o2 = 8; o2 > 0; o2 >>= 1)
                a += __shfl_down_sync(0xFFFFu, a, o2, 16);
            if (t == 0) outH[r] = inv * (ft * a + iv * kqt);
        }

        A0 = B0; A1 = B1;
    }
}

// ---------------- launch ----------------
extern "C" void kernel_launch(void* const* d_in, const int* in_sizes, int n_in,
                              void* d_out, int out_size)
{
    const float* x      = (const float*)d_in[0];
    const float* cp     = (const float*)d_in[1];
    const float* n_prev = (const float*)d_in[2];
    const float* Wq     = (const float*)d_in[3];
    const float* bq     = (const float*)d_in[4];
    const float* Wk     = (const float*)d_in[5];
    const float* bk     = (const float*)d_in[6];
    const float* Wv     = (const float*)d_in[7];
    const float* bV     = (const float*)d_in[8];
    const float* Wi     = (const float*)d_in[9];
    const float* bi     = (const float*)d_in[10];
    const float* Wf     = (const float*)d_in[11];
    const float* bf     = (const float*)d_in[12];
    const float* Wo     = (const float*)d_in[13];
    const float* bo     = (const float*)d_in[14];

    float* out  = (float*)d_out;
    float* outH = out;                        // ht: M
    float* outC = out + MM;                   // C : M*M
    float* outN = out + MM + (size_t)MM * MM; // n : M

    mv_kernel<<<GRID_MV, 256>>>(x, Wq, bq, Wk, bk, Wv, bV);
    nred_kernel<<<1, 1024>>>(x, Wi, bi, Wf, bf, Wo, bo, n_prev, outN);
    cp_kernel<<<GRID_CP, 512>>>(cp, outC, outH);
}